// round 9
// baseline (speedup 1.0000x reference)
#include <cuda_runtime.h>
#include <cuda_bf16.h>
#include <cstdint>

// Inputs: 0 positions f32 (N)*3 | 1 cell f32 9 | 2 cutoffs f32 2
//         3 shifts i32 S*3 | 4 ml_idx i32 | 5 mm_idx i32
// Output (f32 flat): [0,2P) idx_i | [2P,4P) idx_j | [4P,10P) offsets(2P x 3)
//                    [10P,12P) d2_full | [12P,16P) masks(2 x 2P)
// P=(S+1)*n_ml*n_mm.  idx_i=[pi,pj], idx_j=[pj,pi], offsets=[-sv,+sv], d2=[d2,d2].
//
// R9: 3-way grid partition for DRAM row locality.
//  (a) pair-compute blocks: d2 + masks ONLY (6 streams, was 10)
//  (b) idx-fill blocks: [0,4P) pi/pj patterns, contiguous 16KB runs/block
//  (c) offsets-fill blocks: [4P,10P) as before
// 10P of 16P floats now written as long contiguous runs (max row-buffer hits).

__device__ __forceinline__ void load_cell(const float* __restrict__ cell,
                                          float c[9]) {
    #pragma unroll
    for (int u = 0; u < 9; u++) c[u] = __ldg(cell + u);
}

__device__ __forceinline__ void shift_vec(const int* __restrict__ shifts, int s,
                                          const float c[9],
                                          float& svx, float& svy, float& svz) {
    float sf0 = 0.f, sf1 = 0.f, sf2 = 0.f;
    if (s > 0) {
        sf0 = (float)__ldg(shifts + (s - 1) * 3 + 0);
        sf1 = (float)__ldg(shifts + (s - 1) * 3 + 1);
        sf2 = (float)__ldg(shifts + (s - 1) * 3 + 2);
    }
    svx = sf0 * c[0] + sf1 * c[3] + sf2 * c[6];
    svy = sf0 * c[1] + sf1 * c[4] + sf2 * c[7];
    svz = sf0 * c[2] + sf1 * c[5] + sf2 * c[8];
}

// offsets fill: 4096 consecutive float4s per block; lane t writes
// f4 = base + t + u*256 (u<16) -> every STG.128 is a contiguous 512B warp txn
__device__ __forceinline__ void offsets_fill(const int* __restrict__ shifts,
                                             const float c[9],
                                             float* __restrict__ out,
                                             long long fb, long long P,
                                             long long P0, int off_aligned)
{
    const long long tot4 = (6 * P) >> 2;
    const long long base4 = fb * 4096;
    if (base4 >= tot4) return;
    float4* dst = reinterpret_cast<float4*>(out + 4 * P);
    const long long halfF = 3 * P;

    if (off_aligned) {
        const long long fbase = base4 * 4;
        const bool negh = fbase < halfF;
        const long long fl = negh ? fbase : fbase - halfF;
        const int s = (int)(fl / (3 * P0));
        float svx, svy, svz;
        shift_vec(shifts, s, c, svx, svy, svz);
        const float X = negh ? -svx : svx;
        const float Y = negh ? -svy : svy;
        const float Z = negh ? -svz : svz;
        const float4 var[3] = { make_float4(X, Y, Z, X),
                                make_float4(Y, Z, X, Y),
                                make_float4(Z, X, Y, Z) };
        long long f4 = base4 + threadIdx.x;
        int v = (int)(f4 % 3);
        #pragma unroll
        for (int u = 0; u < 16; u++) {
            if (f4 < tot4) dst[f4] = var[v];
            f4 += 256;                          // +256 ≡ +1 (mod 3)
            v++; if (v == 3) v = 0;
        }
    } else {
        for (int u = 0; u < 16; u++) {
            long long f4 = base4 + threadIdx.x + (long long)u * 256;
            if (f4 >= tot4) break;
            #pragma unroll
            for (int w = 0; w < 4; w++) {
                long long f = f4 * 4 + w;
                const bool negh = f < halfF;
                const long long fl = negh ? f : f - halfF;
                const long long row = fl / 3;
                const int comp = (int)(fl - row * 3);
                const int s = (int)(row / P0);
                float svx, svy, svz;
                shift_vec(shifts, s, c, svx, svy, svz);
                float val = (comp == 0) ? svx : (comp == 1) ? svy : svz;
                if (negh) val = -val;
                out[4 * P + f] = val;
            }
        }
    }
}

// idx fill: region [0,4P). Quarters: 0=pi, 1=pj, 2=pj, 3=pi.
// 4096 float4s per block, lane-contiguous 512B warp txns.
// Requires P%4==0, P0%4==0, n_mm%4==0 (checked host-side via fast_ok).
__device__ __forceinline__ void idx_fill(const int* __restrict__ ml_idx,
                                         const int* __restrict__ mm_idx,
                                         float* __restrict__ out,
                                         long long fb, long long P,
                                         long long P0, int n_mm)
{
    const long long tot4 = P;              // 4P floats / 4
    const long long q4   = P >> 2;         // float4s per quarter
    const long long base4 = fb * 4096;
    if (base4 >= tot4) return;
    float4* dst = reinterpret_cast<float4*>(out);

    #pragma unroll
    for (int u = 0; u < 16; u++) {
        const long long f4 = base4 + threadIdx.x + (long long)u * 256;
        if (f4 >= tot4) break;
        const int q = (int)(f4 / q4);
        const long long rem = (f4 - (long long)q * q4) * 4;   // float offset in quarter
        const long long local = rem % P0;
        float4 v;
        if (q == 0 || q == 3) {
            // pi pattern: constant over each n_mm run
            const int i = (int)(local / n_mm);
            const float fi = (float)__ldg(ml_idx + i);
            v = make_float4(fi, fi, fi, fi);
        } else {
            // pj pattern: mm_idx sequence tiled
            const int j0 = (int)(local % n_mm);
            const int4 jv = __ldg(reinterpret_cast<const int4*>(mm_idx + j0));
            v = make_float4((float)jv.x, (float)jv.y, (float)jv.z, (float)jv.w);
        }
        dst[f4] = v;
    }
}

// ─────────── fast kernel: pair-compute (d2+masks) + both fills ───────────────
__global__ __launch_bounds__(256)
void nbrlist_sloop(const float* __restrict__ pos,
                   const float* __restrict__ cell,
                   const float* __restrict__ cutoffs,
                   const int*   __restrict__ shifts,
                   const int*   __restrict__ ml_idx,
                   const int*   __restrict__ mm_idx,
                   float* __restrict__ out,
                   int n_ml, int n_mm, int S_img, long long P,
                   long long pairBlocks, long long idxBlocks,
                   int jchunks, int off_aligned)
{
    const long long P0 = (long long)n_ml * n_mm;

    if (blockIdx.x >= (unsigned)(pairBlocks + idxBlocks)) {
        float c[9];
        load_cell(cell, c);
        offsets_fill(shifts, c, out,
                     (long long)blockIdx.x - pairBlocks - idxBlocks,
                     P, P0, off_aligned);
        return;
    }
    if (blockIdx.x >= (unsigned)pairBlocks) {
        idx_fill(ml_idx, mm_idx, out, (long long)blockIdx.x - pairBlocks,
                 P, P0, n_mm);
        return;
    }

    float c[9];
    load_cell(cell, c);

    const int bi = (int)blockIdx.x;
    const int i  = bi / jchunks;
    const int jc = bi - i * jchunks;
    const int j0 = jc * 1024 + (int)threadIdx.x * 4;

    const float cut0 = __ldg(cutoffs + 0), cut1 = __ldg(cutoffs + 1);
    const float c0sq = cut0 * cut0, c1sq = cut1 * cut1;

    const int ia = __ldg(ml_idx + i);
    const float pix0 = __ldg(pos + 3 * ia + 0);
    const float piy0 = __ldg(pos + 3 * ia + 1);
    const float piz0 = __ldg(pos + 3 * ia + 2);

    const int4 jv = __ldg(reinterpret_cast<const int4*>(mm_idx + j0));
    float pjx[4], pjy[4], pjz[4];

    const bool contig = (jv.w == jv.x + 3) && (((3 * jv.x) & 3) == 0);
    if (contig) {
        const float4* pb = reinterpret_cast<const float4*>(pos + 3 * jv.x);
        const float4 v0 = __ldg(pb + 0);
        const float4 v1 = __ldg(pb + 1);
        const float4 v2 = __ldg(pb + 2);
        pjx[0] = v0.x; pjy[0] = v0.y; pjz[0] = v0.z;
        pjx[1] = v0.w; pjy[1] = v1.x; pjz[1] = v1.y;
        pjx[2] = v1.z; pjy[2] = v1.w; pjz[2] = v2.x;
        pjx[3] = v2.y; pjy[3] = v2.z; pjz[3] = v2.w;
    } else {
        const int jidx[4] = {jv.x, jv.y, jv.z, jv.w};
        #pragma unroll
        for (int u = 0; u < 4; u++) {
            pjx[u] = __ldg(pos + 3 * jidx[u] + 0);
            pjy[u] = __ldg(pos + 3 * jidx[u] + 1);
            pjz[u] = __ldg(pos + 3 * jidx[u] + 2);
        }
    }

    const long long base_d2 = 10 * P;
    const long long base_mk = 12 * P;
    const long long prow = (long long)i * n_mm + j0;

    for (int s = 0; s < S_img; s++) {
        float svx, svy, svz;
        shift_vec(shifts, s, c, svx, svy, svz);
        const float pix = pix0 + svx;
        const float piy = piy0 + svy;
        const float piz = piz0 + svz;

        float d2v[4];
        #pragma unroll
        for (int u = 0; u < 4; u++) {
            const float dx = pix - pjx[u];
            const float dy = piy - pjy[u];
            const float dz = piz - pjz[u];
            d2v[u] = dx * dx + dy * dy + dz * dz;
        }

        const long long p = (long long)s * P0 + prow;
        const float4 v_d2 = make_float4(d2v[0], d2v[1], d2v[2], d2v[3]);

        *reinterpret_cast<float4*>(out + base_d2 + p)     = v_d2;
        *reinterpret_cast<float4*>(out + base_d2 + P + p) = v_d2;

        const float4 m0 = make_float4(d2v[0] < c0sq ? 1.f : 0.f,
                                      d2v[1] < c0sq ? 1.f : 0.f,
                                      d2v[2] < c0sq ? 1.f : 0.f,
                                      d2v[3] < c0sq ? 1.f : 0.f);
        const float4 m1 = make_float4(d2v[0] < c1sq ? 1.f : 0.f,
                                      d2v[1] < c1sq ? 1.f : 0.f,
                                      d2v[2] < c1sq ? 1.f : 0.f,
                                      d2v[3] < c1sq ? 1.f : 0.f);
        *reinterpret_cast<float4*>(out + base_mk + p)         = m0;
        *reinterpret_cast<float4*>(out + base_mk + P + p)     = m0;
        *reinterpret_cast<float4*>(out + base_mk + 2 * P + p) = m1;
        *reinterpret_cast<float4*>(out + base_mk + 3 * P + p) = m1;
    }
}

// ───────────────────────── generic fallback kernel ──────────────────────────
__global__ __launch_bounds__(256)
void nbrlist_generic(const float* __restrict__ pos,
                     const float* __restrict__ cell,
                     const float* __restrict__ cutoffs,
                     const int*   __restrict__ shifts,
                     const int*   __restrict__ ml_idx,
                     const int*   __restrict__ mm_idx,
                     float* __restrict__ out,
                     int n_ml, int n_mm, int S_img, long long P,
                     long long pairBlocks, int off_aligned)
{
    const long long P0 = (long long)n_ml * n_mm;
    float c[9];
    load_cell(cell, c);

    if (blockIdx.x >= (unsigned)pairBlocks) {
        offsets_fill(shifts, c, out, (long long)blockIdx.x - pairBlocks,
                     P, P0, off_aligned);
        return;
    }

    long long tid = (long long)blockIdx.x * blockDim.x + threadIdx.x;
    long long p0 = tid * 4;
    if (p0 >= P) return;

    const float cut0 = __ldg(cutoffs + 0), cut1 = __ldg(cutoffs + 1);
    const float c0sq = cut0 * cut0, c1sq = cut1 * cut1;

    for (int u = 0; u < 4; u++) {
        long long pp = p0 + u;
        if (pp >= P) break;
        int ss = (int)(pp / P0);
        long long kk = pp - (long long)ss * P0;
        int ii = (int)(kk / n_mm);
        int jj = (int)(kk - (long long)ii * n_mm);

        float svx, svy, svz;
        shift_vec(shifts, ss, c, svx, svy, svz);

        const int ia = __ldg(ml_idx + ii);
        const int ja = __ldg(mm_idx + jj);
        const float dx = __ldg(pos + 3 * ia + 0) - __ldg(pos + 3 * ja + 0) + svx;
        const float dy = __ldg(pos + 3 * ia + 1) - __ldg(pos + 3 * ja + 1) + svy;
        const float dz = __ldg(pos + 3 * ia + 2) - __ldg(pos + 3 * ja + 2) + svz;
        const float d2 = dx * dx + dy * dy + dz * dz;
        const float fi = (float)ia, fj = (float)ja;

        out[pp]         = fi;
        out[P + pp]     = fj;
        out[2 * P + pp] = fj;
        out[3 * P + pp] = fi;
        out[10 * P + pp]     = d2;
        out[10 * P + P + pp] = d2;
        const float m0 = d2 < c0sq ? 1.f : 0.f;
        const float m1 = d2 < c1sq ? 1.f : 0.f;
        out[12 * P + pp]         = m0;
        out[12 * P + P + pp]     = m0;
        out[12 * P + 2 * P + pp] = m1;
        out[12 * P + 3 * P + pp] = m1;
    }
}

extern "C" void kernel_launch(void* const* d_in, const int* in_sizes, int n_in,
                              void* d_out, int out_size)
{
    const float* pos     = (const float*)d_in[0];
    const float* cell    = (const float*)d_in[1];
    const float* cutoffs = (const float*)d_in[2];
    const int*   shifts  = (const int*)d_in[3];
    const int*   ml_idx  = (const int*)d_in[4];
    const int*   mm_idx  = (const int*)d_in[5];

    const int n_ml  = in_sizes[4];
    const int n_mm  = in_sizes[5];
    const int S     = in_sizes[3] / 3;
    const int S_img = S + 1;
    const long long P0 = (long long)n_ml * n_mm;
    const long long P  = (long long)S_img * P0;

    const int threads = 256;

    const long long tot4off   = (6 * P) / 4;
    const long long offBlocks = (tot4off + 4095) / 4096;
    const int off_aligned = (((3 * P0) % 16384) == 0) && (((3 * P) % 16384) == 0)
                            && ((P % 4) == 0) ? 1 : 0;

    // fast path needs: j-chunking, vector alignment, quarter alignment
    const bool fast_ok = (n_mm % 1024 == 0) && ((P % 4) == 0)
                         && ((P0 % 4) == 0) && ((n_mm % 4) == 0);

    if (fast_ok) {
        const int jchunks = n_mm / 1024;
        const long long pairBlocks = (long long)n_ml * jchunks;
        const long long idxBlocks  = (P + 4095) / 4096;   // P float4s in [0,4P)
        const long long totalBlocks = pairBlocks + idxBlocks + offBlocks;
        nbrlist_sloop<<<(unsigned)totalBlocks, threads>>>(
            pos, cell, cutoffs, shifts, ml_idx, mm_idx,
            (float*)d_out, n_ml, n_mm, S_img, P,
            pairBlocks, idxBlocks, jchunks, off_aligned);
    } else {
        const long long n_groups   = (P + 3) / 4;
        const long long pairBlocks = (n_groups + threads - 1) / threads;
        const long long totalBlocks = pairBlocks + offBlocks;
        nbrlist_generic<<<(unsigned)totalBlocks, threads>>>(
            pos, cell, cutoffs, shifts, ml_idx, mm_idx,
            (float*)d_out, n_ml, n_mm, S_img, P, pairBlocks, off_aligned);
    }
}

// round 10
// speedup vs baseline: 1.1507x; 1.1507x over previous
#include <cuda_runtime.h>
#include <cuda_bf16.h>
#include <cstdint>

// Inputs: 0 positions f32 (N)*3 | 1 cell f32 9 | 2 cutoffs f32 2
//         3 shifts i32 S*3 | 4 ml_idx i32 | 5 mm_idx i32
// Output (f32 flat): [0,2P) idx_i | [2P,4P) idx_j | [4P,10P) offsets(2P x 3)
//                    [10P,12P) d2_full | [12P,16P) masks(2 x 2P)
// P=(S+1)*n_ml*n_mm.  idx_i=[pi,pj], idx_j=[pj,pi], offsets=[-sv,+sv], d2=[d2,d2].
//
// R10 = R9 partition with strength-reduced idx_fill (all 64-bit div/mod
// hoisted to block scope; inner loop is add/compare only).
//  (a) pair-compute blocks: d2 + masks only
//  (b) idx-fill blocks: [0,4P), contiguous 16KB runs, 1 div/thread
//  (c) offsets-fill blocks: [4P,10P)

__device__ __forceinline__ void load_cell(const float* __restrict__ cell,
                                          float c[9]) {
    #pragma unroll
    for (int u = 0; u < 9; u++) c[u] = __ldg(cell + u);
}

__device__ __forceinline__ void shift_vec(const int* __restrict__ shifts, int s,
                                          const float c[9],
                                          float& svx, float& svy, float& svz) {
    float sf0 = 0.f, sf1 = 0.f, sf2 = 0.f;
    if (s > 0) {
        sf0 = (float)__ldg(shifts + (s - 1) * 3 + 0);
        sf1 = (float)__ldg(shifts + (s - 1) * 3 + 1);
        sf2 = (float)__ldg(shifts + (s - 1) * 3 + 2);
    }
    svx = sf0 * c[0] + sf1 * c[3] + sf2 * c[6];
    svy = sf0 * c[1] + sf1 * c[4] + sf2 * c[7];
    svz = sf0 * c[2] + sf1 * c[5] + sf2 * c[8];
}

// offsets fill: 4096 consecutive float4s per block; lane t writes
// f4 = base + t + u*256 -> every STG.128 is a contiguous 512B warp txn
__device__ __forceinline__ void offsets_fill(const int* __restrict__ shifts,
                                             const float c[9],
                                             float* __restrict__ out,
                                             long long fb, long long P,
                                             long long P0, int off_aligned)
{
    const long long tot4 = (6 * P) >> 2;
    const long long base4 = fb * 4096;
    if (base4 >= tot4) return;
    float4* dst = reinterpret_cast<float4*>(out + 4 * P);
    const long long halfF = 3 * P;

    if (off_aligned) {
        const long long fbase = base4 * 4;
        const bool negh = fbase < halfF;
        const long long fl = negh ? fbase : fbase - halfF;
        const int s = (int)(fl / (3 * P0));
        float svx, svy, svz;
        shift_vec(shifts, s, c, svx, svy, svz);
        const float X = negh ? -svx : svx;
        const float Y = negh ? -svy : svy;
        const float Z = negh ? -svz : svz;
        const float4 var[3] = { make_float4(X, Y, Z, X),
                                make_float4(Y, Z, X, Y),
                                make_float4(Z, X, Y, Z) };
        long long f4 = base4 + threadIdx.x;
        int v = (int)(f4 % 3);
        #pragma unroll
        for (int u = 0; u < 16; u++) {
            if (f4 < tot4) dst[f4] = var[v];
            f4 += 256;                          // +256 ≡ +1 (mod 3)
            v++; if (v == 3) v = 0;
        }
    } else {
        for (int u = 0; u < 16; u++) {
            long long f4 = base4 + threadIdx.x + (long long)u * 256;
            if (f4 >= tot4) break;
            #pragma unroll
            for (int w = 0; w < 4; w++) {
                long long f = f4 * 4 + w;
                const bool negh = f < halfF;
                const long long fl = negh ? f : f - halfF;
                const long long row = fl / 3;
                const int comp = (int)(fl - row * 3);
                const int s = (int)(row / P0);
                float svx, svy, svz;
                shift_vec(shifts, s, c, svx, svy, svz);
                float val = (comp == 0) ? svx : (comp == 1) ? svy : svz;
                if (negh) val = -val;
                out[4 * P + f] = val;
            }
        }
    }
}

// idx fill: region [0,4P). Quarters: 0=pi, 1=pj, 2=pj, 3=pi.
// Alignment (host-gated): (P0/4)%4096==0 and (P/4)%4096==0 -> each block lies
// in ONE quarter and ONE P0 tile. One 32-bit div per thread; inner loop is
// add/compare. n_mm%1024==0 guarantees single-wrap j stepping.
__device__ __forceinline__ void idx_fill(const int* __restrict__ ml_idx,
                                         const int* __restrict__ mm_idx,
                                         float* __restrict__ out,
                                         long long fb, long long P,
                                         long long P0, int n_mm)
{
    const long long tot4 = P;              // float4s in [0,4P)
    const long long q4   = P >> 2;         // float4s per quarter
    const long long base4 = fb * 4096;
    if (base4 >= tot4) return;
    float4* dst = reinterpret_cast<float4*>(out);

    const int q = (int)(base4 / q4);                    // constant per block
    const long long rem4 = base4 - (long long)q * q4;
    const int local4 = (int)(rem4 % (P0 >> 2));         // fits 32-bit
    int f = (local4 + (int)threadIdx.x) * 4;            // float offset in P0 tile
    const bool is_pi = (q == 0 || q == 3);

    int i = f / n_mm;                                   // one 32-bit div
    int j = f - i * n_mm;

    long long f4 = base4 + threadIdx.x;
    #pragma unroll
    for (int u = 0; u < 16; u++) {
        if (f4 < tot4) {
            float4 v;
            if (is_pi) {
                const float fi = (float)__ldg(ml_idx + i);
                v = make_float4(fi, fi, fi, fi);
            } else {
                const int4 jv = __ldg(reinterpret_cast<const int4*>(mm_idx + j));
                v = make_float4((float)jv.x, (float)jv.y,
                                (float)jv.z, (float)jv.w);
            }
            dst[f4] = v;
        }
        f4 += 256;                                      // +1024 floats
        j += 1024;
        if (j >= n_mm) { j -= n_mm; i++; }
    }
}

// ─────────── fast kernel: pair-compute (d2+masks) + both fills ───────────────
__global__ __launch_bounds__(256)
void nbrlist_sloop(const float* __restrict__ pos,
                   const float* __restrict__ cell,
                   const float* __restrict__ cutoffs,
                   const int*   __restrict__ shifts,
                   const int*   __restrict__ ml_idx,
                   const int*   __restrict__ mm_idx,
                   float* __restrict__ out,
                   int n_ml, int n_mm, int S_img, long long P,
                   long long pairBlocks, long long idxBlocks,
                   int jchunks, int off_aligned)
{
    const long long P0 = (long long)n_ml * n_mm;

    if (blockIdx.x >= (unsigned)(pairBlocks + idxBlocks)) {
        float c[9];
        load_cell(cell, c);
        offsets_fill(shifts, c, out,
                     (long long)blockIdx.x - pairBlocks - idxBlocks,
                     P, P0, off_aligned);
        return;
    }
    if (blockIdx.x >= (unsigned)pairBlocks) {
        idx_fill(ml_idx, mm_idx, out, (long long)blockIdx.x - pairBlocks,
                 P, P0, n_mm);
        return;
    }

    float c[9];
    load_cell(cell, c);

    const int bi = (int)blockIdx.x;
    const int i  = bi / jchunks;
    const int jc = bi - i * jchunks;
    const int j0 = jc * 1024 + (int)threadIdx.x * 4;

    const float cut0 = __ldg(cutoffs + 0), cut1 = __ldg(cutoffs + 1);
    const float c0sq = cut0 * cut0, c1sq = cut1 * cut1;

    const int ia = __ldg(ml_idx + i);
    const float pix0 = __ldg(pos + 3 * ia + 0);
    const float piy0 = __ldg(pos + 3 * ia + 1);
    const float piz0 = __ldg(pos + 3 * ia + 2);

    const int4 jv = __ldg(reinterpret_cast<const int4*>(mm_idx + j0));
    float pjx[4], pjy[4], pjz[4];

    const bool contig = (jv.w == jv.x + 3) && (((3 * jv.x) & 3) == 0);
    if (contig) {
        const float4* pb = reinterpret_cast<const float4*>(pos + 3 * jv.x);
        const float4 v0 = __ldg(pb + 0);
        const float4 v1 = __ldg(pb + 1);
        const float4 v2 = __ldg(pb + 2);
        pjx[0] = v0.x; pjy[0] = v0.y; pjz[0] = v0.z;
        pjx[1] = v0.w; pjy[1] = v1.x; pjz[1] = v1.y;
        pjx[2] = v1.z; pjy[2] = v1.w; pjz[2] = v2.x;
        pjx[3] = v2.y; pjy[3] = v2.z; pjz[3] = v2.w;
    } else {
        const int jidx[4] = {jv.x, jv.y, jv.z, jv.w};
        #pragma unroll
        for (int u = 0; u < 4; u++) {
            pjx[u] = __ldg(pos + 3 * jidx[u] + 0);
            pjy[u] = __ldg(pos + 3 * jidx[u] + 1);
            pjz[u] = __ldg(pos + 3 * jidx[u] + 2);
        }
    }

    const long long base_d2 = 10 * P;
    const long long base_mk = 12 * P;
    const long long prow = (long long)i * n_mm + j0;

    for (int s = 0; s < S_img; s++) {
        float svx, svy, svz;
        shift_vec(shifts, s, c, svx, svy, svz);
        const float pix = pix0 + svx;
        const float piy = piy0 + svy;
        const float piz = piz0 + svz;

        float d2v[4];
        #pragma unroll
        for (int u = 0; u < 4; u++) {
            const float dx = pix - pjx[u];
            const float dy = piy - pjy[u];
            const float dz = piz - pjz[u];
            d2v[u] = dx * dx + dy * dy + dz * dz;
        }

        const long long p = (long long)s * P0 + prow;
        const float4 v_d2 = make_float4(d2v[0], d2v[1], d2v[2], d2v[3]);

        *reinterpret_cast<float4*>(out + base_d2 + p)     = v_d2;
        *reinterpret_cast<float4*>(out + base_d2 + P + p) = v_d2;

        const float4 m0 = make_float4(d2v[0] < c0sq ? 1.f : 0.f,
                                      d2v[1] < c0sq ? 1.f : 0.f,
                                      d2v[2] < c0sq ? 1.f : 0.f,
                                      d2v[3] < c0sq ? 1.f : 0.f);
        const float4 m1 = make_float4(d2v[0] < c1sq ? 1.f : 0.f,
                                      d2v[1] < c1sq ? 1.f : 0.f,
                                      d2v[2] < c1sq ? 1.f : 0.f,
                                      d2v[3] < c1sq ? 1.f : 0.f);
        *reinterpret_cast<float4*>(out + base_mk + p)         = m0;
        *reinterpret_cast<float4*>(out + base_mk + P + p)     = m0;
        *reinterpret_cast<float4*>(out + base_mk + 2 * P + p) = m1;
        *reinterpret_cast<float4*>(out + base_mk + 3 * P + p) = m1;
    }
}

// ───────────────────────── generic fallback kernel ──────────────────────────
__global__ __launch_bounds__(256)
void nbrlist_generic(const float* __restrict__ pos,
                     const float* __restrict__ cell,
                     const float* __restrict__ cutoffs,
                     const int*   __restrict__ shifts,
                     const int*   __restrict__ ml_idx,
                     const int*   __restrict__ mm_idx,
                     float* __restrict__ out,
                     int n_ml, int n_mm, int S_img, long long P,
                     long long pairBlocks, int off_aligned)
{
    const long long P0 = (long long)n_ml * n_mm;
    float c[9];
    load_cell(cell, c);

    if (blockIdx.x >= (unsigned)pairBlocks) {
        offsets_fill(shifts, c, out, (long long)blockIdx.x - pairBlocks,
                     P, P0, off_aligned);
        return;
    }

    long long tid = (long long)blockIdx.x * blockDim.x + threadIdx.x;
    long long p0 = tid * 4;
    if (p0 >= P) return;

    const float cut0 = __ldg(cutoffs + 0), cut1 = __ldg(cutoffs + 1);
    const float c0sq = cut0 * cut0, c1sq = cut1 * cut1;

    for (int u = 0; u < 4; u++) {
        long long pp = p0 + u;
        if (pp >= P) break;
        int ss = (int)(pp / P0);
        long long kk = pp - (long long)ss * P0;
        int ii = (int)(kk / n_mm);
        int jj = (int)(kk - (long long)ii * n_mm);

        float svx, svy, svz;
        shift_vec(shifts, ss, c, svx, svy, svz);

        const int ia = __ldg(ml_idx + ii);
        const int ja = __ldg(mm_idx + jj);
        const float dx = __ldg(pos + 3 * ia + 0) - __ldg(pos + 3 * ja + 0) + svx;
        const float dy = __ldg(pos + 3 * ia + 1) - __ldg(pos + 3 * ja + 1) + svy;
        const float dz = __ldg(pos + 3 * ia + 2) - __ldg(pos + 3 * ja + 2) + svz;
        const float d2 = dx * dx + dy * dy + dz * dz;
        const float fi = (float)ia, fj = (float)ja;

        out[pp]         = fi;
        out[P + pp]     = fj;
        out[2 * P + pp] = fj;
        out[3 * P + pp] = fi;
        out[10 * P + pp]     = d2;
        out[10 * P + P + pp] = d2;
        const float m0 = d2 < c0sq ? 1.f : 0.f;
        const float m1 = d2 < c1sq ? 1.f : 0.f;
        out[12 * P + pp]         = m0;
        out[12 * P + P + pp]     = m0;
        out[12 * P + 2 * P + pp] = m1;
        out[12 * P + 3 * P + pp] = m1;
    }
}

extern "C" void kernel_launch(void* const* d_in, const int* in_sizes, int n_in,
                              void* d_out, int out_size)
{
    const float* pos     = (const float*)d_in[0];
    const float* cell    = (const float*)d_in[1];
    const float* cutoffs = (const float*)d_in[2];
    const int*   shifts  = (const int*)d_in[3];
    const int*   ml_idx  = (const int*)d_in[4];
    const int*   mm_idx  = (const int*)d_in[5];

    const int n_ml  = in_sizes[4];
    const int n_mm  = in_sizes[5];
    const int S     = in_sizes[3] / 3;
    const int S_img = S + 1;
    const long long P0 = (long long)n_ml * n_mm;
    const long long P  = (long long)S_img * P0;

    const int threads = 256;

    const long long tot4off   = (6 * P) / 4;
    const long long offBlocks = (tot4off + 4095) / 4096;
    const int off_aligned = (((3 * P0) % 16384) == 0) && (((3 * P) % 16384) == 0)
                            && ((P % 4) == 0) ? 1 : 0;

    // fast path gates: j-chunking; idx-fill block alignment
    //   (P0/4)%4096==0  <=>  P0%16384==0   (block within one P0 tile)
    //   (P/4)%4096==0   <=>  P%16384==0    (block within one quarter)
    const bool fast_ok = (n_mm % 1024 == 0)
                         && ((P0 % 16384) == 0) && ((P % 16384) == 0);

    if (fast_ok) {
        const int jchunks = n_mm / 1024;
        const long long pairBlocks = (long long)n_ml * jchunks;
        const long long idxBlocks  = (P + 4095) / 4096;   // P float4s in [0,4P)
        const long long totalBlocks = pairBlocks + idxBlocks + offBlocks;
        nbrlist_sloop<<<(unsigned)totalBlocks, threads>>>(
            pos, cell, cutoffs, shifts, ml_idx, mm_idx,
            (float*)d_out, n_ml, n_mm, S_img, P,
            pairBlocks, idxBlocks, jchunks, off_aligned);
    } else {
        const long long n_groups   = (P + 3) / 4;
        const long long pairBlocks = (n_groups + threads - 1) / threads;
        const long long totalBlocks = pairBlocks + offBlocks;
        nbrlist_generic<<<(unsigned)totalBlocks, threads>>>(
            pos, cell, cutoffs, shifts, ml_idx, mm_idx,
            (float*)d_out, n_ml, n_mm, S_img, P, pairBlocks, off_aligned);
    }
}